// round 2
// baseline (speedup 1.0000x reference)
#include <cuda_runtime.h>
#include <math_constants.h>

#define BSZ 16
#define SEQ 2048
#define DK  64
#define BM  64
#define BN  64

// Scratch: transposed Q and K, [b][d][s]  (device globals = sanctioned scratch)
__device__ float g_QT[BSZ * DK * SEQ];
__device__ float g_KT[BSZ * DK * SEQ];

// [b][s][d] -> [b][d][s]
__global__ void transpose_kernel(const float* __restrict__ in, int which) {
    __shared__ float tile[32][33];
    int b  = blockIdx.z;
    int s0 = blockIdx.x * 32;
    int d0 = blockIdx.y * 32;
    int tx = threadIdx.x, ty = threadIdx.y;
    const float* ip = in + (size_t)b * SEQ * DK;
    float* op = (which ? g_KT : g_QT) + (size_t)b * DK * SEQ;
    #pragma unroll
    for (int i = ty; i < 32; i += 8)
        tile[i][tx] = ip[(s0 + i) * DK + (d0 + tx)];
    __syncthreads();
    #pragma unroll
    for (int i = ty; i < 32; i += 8)
        op[(d0 + i) * SEQ + (s0 + tx)] = tile[tx][i];
}

__global__ __launch_bounds__(256, 2)
void attn_kernel(const float* __restrict__ V,
                 const float* __restrict__ Kr,
                 float* __restrict__ out) {
    extern __shared__ float smem[];
    float* qT  = smem;            // [64][64]  qT[k][uu]
    float* kT  = qT  + 64 * 64;   // [64][64]  kT[k][tt]
    float* vs  = kT  + 64 * 64;   // [64][64]  vs[tt][d]
    float* as_ = vs  + 64 * 64;   // [64][64]  A tile row-major
    float* kr  = as_ + 64 * 64;   // [64][128] kr[k][ci]

    int b   = blockIdx.y;
    int u0  = (int)(gridDim.x - 1 - blockIdx.x) * BM;  // big blocks first
    int tid = threadIdx.x;
    int tx  = tid & 15, ty = tid >> 4;
    int r0  = ty << 2, c0 = tx << 2;

    const float* QTb = g_QT + (size_t)b * DK * SEQ;
    const float* KTb = g_KT + (size_t)b * DK * SEQ;
    const float* Vb  = V    + (size_t)b * SEQ * DK;

    // Q tile, loaded once (k-major)
    #pragma unroll
    for (int x = tid; x < 64 * 16; x += 256) {
        int row = x >> 4, col = (x & 15) << 2;
        *(float4*)&qT[row * 64 + col] = *(const float4*)&QTb[row * SEQ + u0 + col];
    }

    float m_i[4], l_i[4], o[16];
    #pragma unroll
    for (int i = 0; i < 4; i++) { m_i[i] = -CUDART_INF_F; l_i[i] = 0.f; }
    #pragma unroll
    for (int i = 0; i < 16; i++) o[i] = 0.f;

    const int nIter = u0 / BN + 1;
    for (int it = 0; it < nIter; ++it) {
        const int t0 = it * BN;
        __syncthreads();  // protect smem reuse from previous iteration

        // K tile (k-major) and V tile (row-major)
        #pragma unroll
        for (int x = tid; x < 64 * 16; x += 256) {
            int row = x >> 4, col = (x & 15) << 2;
            *(float4*)&kT[row * 64 + col] = *(const float4*)&KTb[row * SEQ + t0 + col];
            *(float4*)&vs[row * 64 + col] = *(const float4*)&Vb[(t0 + row) * DK + col];
        }
        // Relpos window: columns c_lo .. c_lo+127 of Krelpos (d-major already)
        const int c_lo = SEQ - BN - u0 + t0;
        #pragma unroll
        for (int x = tid; x < 64 * 32; x += 256) {
            int row = x >> 5, col = (x & 31) << 2;
            int c = c_lo + col;
            if (c + 3 <= SEQ - 1) {
                *(float4*)&kr[row * 128 + col] = *(const float4*)&Kr[row * SEQ + c];
            } else {  // clamp (values only land in masked region)
                float4 t;
                t.x = Kr[row * SEQ + min(c + 0, SEQ - 1)];
                t.y = Kr[row * SEQ + min(c + 1, SEQ - 1)];
                t.z = Kr[row * SEQ + min(c + 2, SEQ - 1)];
                t.w = Kr[row * SEQ + min(c + 3, SEQ - 1)];
                *(float4*)&kr[row * 128 + col] = t;
            }
        }
        __syncthreads();

        // S = Q K^T + Q Krel(window), 4x4 micro-tile per thread
        float s[16];
        #pragma unroll
        for (int i = 0; i < 16; i++) s[i] = 0.f;
        const int cb = c0 - r0 + 60;  // multiple of 4 -> aligned float4 window
        #pragma unroll 8
        for (int k = 0; k < 64; k++) {
            float4 q4  = *(const float4*)&qT[k * 64 + r0];
            float4 k4  = *(const float4*)&kT[k * 64 + c0];
            float4 kr0 = *(const float4*)&kr[k * 128 + cb];
            float4 kr1 = *(const float4*)&kr[k * 128 + cb + 4];
            float qv[4]  = {q4.x, q4.y, q4.z, q4.w};
            float kv[4]  = {k4.x, k4.y, k4.z, k4.w};
            float krv[8] = {kr0.x, kr0.y, kr0.z, kr0.w, kr1.x, kr1.y, kr1.z, kr1.w};
            #pragma unroll
            for (int i = 0; i < 4; i++)
                #pragma unroll
                for (int j = 0; j < 4; j++) {
                    s[i * 4 + j] = fmaf(qv[i], kv[j], s[i * 4 + j]);
                    s[i * 4 + j] = fmaf(qv[i], krv[j - i + 3], s[i * 4 + j]);
                }
        }
        #pragma unroll
        for (int i = 0; i < 16; i++) s[i] *= 0.125f;  // 1/sqrt(64)

        if (t0 == u0) {  // diagonal tile: causal mask
            #pragma unroll
            for (int i = 0; i < 4; i++)
                #pragma unroll
                for (int j = 0; j < 4; j++)
                    if (c0 + j > r0 + i) s[i * 4 + j] = -CUDART_INF_F;
        }

        // Online softmax per row (rows replicated across the 16 tx lanes)
        #pragma unroll
        for (int i = 0; i < 4; i++) {
            float rm = fmaxf(fmaxf(s[i * 4 + 0], s[i * 4 + 1]),
                             fmaxf(s[i * 4 + 2], s[i * 4 + 3]));
            #pragma unroll
            for (int off = 1; off < 16; off <<= 1)
                rm = fmaxf(rm, __shfl_xor_sync(0xffffffffu, rm, off));
            float mn    = fmaxf(m_i[i], rm);
            float alpha = __expf(m_i[i] - mn);
            m_i[i] = mn;
            float ps = 0.f;
            #pragma unroll
            for (int j = 0; j < 4; j++) {
                float p = __expf(s[i * 4 + j] - mn);
                s[i * 4 + j] = p;
                ps += p;
            }
            #pragma unroll
            for (int off = 1; off < 16; off <<= 1)
                ps += __shfl_xor_sync(0xffffffffu, ps, off);
            l_i[i] = l_i[i] * alpha + ps;
            #pragma unroll
            for (int j = 0; j < 4; j++) o[i * 4 + j] *= alpha;
            float4 pv = make_float4(s[i * 4 + 0], s[i * 4 + 1], s[i * 4 + 2], s[i * 4 + 3]);
            *(float4*)&as_[(r0 + i) * 64 + c0] = pv;
        }
        __syncthreads();

        // O += A @ V   (4 rows x 4 output cols, 4-wide tt chunks)
        #pragma unroll 4
        for (int tt = 0; tt < 64; tt += 4) {
            float4 a0 = *(const float4*)&as_[(r0 + 0) * 64 + tt];
            float4 a1 = *(const float4*)&as_[(r0 + 1) * 64 + tt];
            float4 a2 = *(const float4*)&as_[(r0 + 2) * 64 + tt];
            float4 a3 = *(const float4*)&as_[(r0 + 3) * 64 + tt];
            float4 v0 = *(const float4*)&vs[(tt + 0) * 64 + c0];
            float4 v1 = *(const float4*)&vs[(tt + 1) * 64 + c0];
            float4 v2 = *(const float4*)&vs[(tt + 2) * 64 + c0];
            float4 v3 = *(const float4*)&vs[(tt + 3) * 64 + c0];
            float av[4][4] = {{a0.x, a0.y, a0.z, a0.w}, {a1.x, a1.y, a1.z, a1.w},
                              {a2.x, a2.y, a2.z, a2.w}, {a3.x, a3.y, a3.z, a3.w}};
            float vv[4][4] = {{v0.x, v0.y, v0.z, v0.w}, {v1.x, v1.y, v1.z, v1.w},
                              {v2.x, v2.y, v2.z, v2.w}, {v3.x, v3.y, v3.z, v3.w}};
            #pragma unroll
            for (int i = 0; i < 4; i++)
                #pragma unroll
                for (int q = 0; q < 4; q++)
                    #pragma unroll
                    for (int j = 0; j < 4; j++)
                        o[i * 4 + j] = fmaf(av[i][q], vv[q][j], o[i * 4 + j]);
        }
    }

    // Epilogue: normalize and store
    float* ob = out + (size_t)b * SEQ * DK;
    #pragma unroll
    for (int i = 0; i < 4; i++) {
        float inv = 1.f / l_i[i];
        float4 r;
        r.x = o[i * 4 + 0] * inv;
        r.y = o[i * 4 + 1] * inv;
        r.z = o[i * 4 + 2] * inv;
        r.w = o[i * 4 + 3] * inv;
        *(float4*)&ob[(size_t)(u0 + r0 + i) * DK + c0] = r;
    }
}

extern "C" void kernel_launch(void* const* d_in, const int* in_sizes, int n_in,
                              void* d_out, int out_size) {
    const float* Q  = (const float*)d_in[0];
    const float* K  = (const float*)d_in[1];
    const float* V  = (const float*)d_in[2];
    const float* Kr = (const float*)d_in[3];
    float* out = (float*)d_out;

    cudaFuncSetAttribute(attn_kernel, cudaFuncAttributeMaxDynamicSharedMemorySize, 98304);

    dim3 tb(32, 8);
    dim3 tg(SEQ / 32, DK / 32, BSZ);
    transpose_kernel<<<tg, tb>>>(Q, 0);
    transpose_kernel<<<tg, tb>>>(K, 1);

    attn_kernel<<<dim3(SEQ / BM, BSZ), 256, 98304>>>(V, Kr, out);
}

// round 3
// speedup vs baseline: 1.0286x; 1.0286x over previous
#include <cuda_runtime.h>
#include <math_constants.h>

#define BSZ 16
#define SEQ 2048
#define DK  64
#define BM  64
#define BN  64

// Scratch: transposed Q and K, [b][d][s]  (device globals = sanctioned scratch)
__device__ float g_QT[BSZ * DK * SEQ];
__device__ float g_KT[BSZ * DK * SEQ];

// [b][s][d] -> [b][d][s]
__global__ void transpose_kernel(const float* __restrict__ in, int which) {
    __shared__ float tile[32][33];
    int b  = blockIdx.z;
    int s0 = blockIdx.x * 32;
    int d0 = blockIdx.y * 32;
    int tx = threadIdx.x, ty = threadIdx.y;
    const float* ip = in + (size_t)b * SEQ * DK;
    float* op = (which ? g_KT : g_QT) + (size_t)b * DK * SEQ;
    #pragma unroll
    for (int i = ty; i < 32; i += 8)
        tile[i][tx] = ip[(s0 + i) * DK + (d0 + tx)];
    __syncthreads();
    #pragma unroll
    for (int i = ty; i < 32; i += 8)
        op[(d0 + i) * SEQ + (s0 + tx)] = tile[tx][i];
}

__global__ __launch_bounds__(256, 2)
void attn_kernel(const float* __restrict__ V,
                 const float* __restrict__ Kr,
                 float* __restrict__ out) {
    extern __shared__ float smem[];
    float* qT  = smem;            // [64][64]  qT[k][uu]
    float* kT  = qT  + 64 * 64;   // [64][64]  kT[k][tt]
    float* vs  = kT  + 64 * 64;   // [64][64]  vs[tt][d]
    float* as_ = vs  + 64 * 64;   // [64][64]  A tile row-major
    float* kr  = as_ + 64 * 64;   // [64][128] kr[k][ci]

    int b   = blockIdx.y;
    int u0  = (int)(gridDim.x - 1 - blockIdx.x) * BM;  // big blocks first
    int tid = threadIdx.x;
    int tx  = tid & 15, ty = tid >> 4;
    int r0  = ty << 2, c0 = tx << 2;

    const float* QTb = g_QT + (size_t)b * DK * SEQ;
    const float* KTb = g_KT + (size_t)b * DK * SEQ;
    const float* Vb  = V    + (size_t)b * SEQ * DK;

    // Q tile, loaded once (k-major)
    #pragma unroll
    for (int x = tid; x < 64 * 16; x += 256) {
        int row = x >> 4, col = (x & 15) << 2;
        *(float4*)&qT[row * 64 + col] = *(const float4*)&QTb[row * SEQ + u0 + col];
    }

    float m_i[4], l_i[4], o[16];
    #pragma unroll
    for (int i = 0; i < 4; i++) { m_i[i] = -CUDART_INF_F; l_i[i] = 0.f; }
    #pragma unroll
    for (int i = 0; i < 16; i++) o[i] = 0.f;

    const int nIter = u0 / BN + 1;
    for (int it = 0; it < nIter; ++it) {
        const int t0 = it * BN;
        __syncthreads();  // protect smem reuse from previous iteration

        // K tile (k-major) and V tile (row-major)
        #pragma unroll
        for (int x = tid; x < 64 * 16; x += 256) {
            int row = x >> 4, col = (x & 15) << 2;
            *(float4*)&kT[row * 64 + col] = *(const float4*)&KTb[row * SEQ + t0 + col];
            *(float4*)&vs[row * 64 + col] = *(const float4*)&Vb[(t0 + row) * DK + col];
        }
        // Relpos window: columns c_lo .. c_lo+127 of Krelpos (d-major already)
        const int c_lo = SEQ - BN - u0 + t0;
        #pragma unroll
        for (int x = tid; x < 64 * 32; x += 256) {
            int row = x >> 5, col = (x & 31) << 2;
            int c = c_lo + col;
            if (c + 3 <= SEQ - 1) {
                *(float4*)&kr[row * 128 + col] = *(const float4*)&Kr[row * SEQ + c];
            } else {  // clamp (values only land in masked region)
                float4 t;
                t.x = Kr[row * SEQ + min(c + 0, SEQ - 1)];
                t.y = Kr[row * SEQ + min(c + 1, SEQ - 1)];
                t.z = Kr[row * SEQ + min(c + 2, SEQ - 1)];
                t.w = Kr[row * SEQ + min(c + 3, SEQ - 1)];
                *(float4*)&kr[row * 128 + col] = t;
            }
        }
        __syncthreads();

        // S = Q K^T + Q Krel(window), 4x4 micro-tile per thread
        float s[16];
        #pragma unroll
        for (int i = 0; i < 16; i++) s[i] = 0.f;
        const int cb = c0 - r0 + 60;  // multiple of 4 -> aligned float4 window
        #pragma unroll 8
        for (int k = 0; k < 64; k++) {
            float4 q4  = *(const float4*)&qT[k * 64 + r0];
            float4 k4  = *(const float4*)&kT[k * 64 + c0];
            float4 kr0 = *(const float4*)&kr[k * 128 + cb];
            float4 kr1 = *(const float4*)&kr[k * 128 + cb + 4];
            float qv[4]  = {q4.x, q4.y, q4.z, q4.w};
            float kv[4]  = {k4.x, k4.y, k4.z, k4.w};
            float krv[8] = {kr0.x, kr0.y, kr0.z, kr0.w, kr1.x, kr1.y, kr1.z, kr1.w};
            #pragma unroll
            for (int i = 0; i < 4; i++)
                #pragma unroll
                for (int j = 0; j < 4; j++) {
                    s[i * 4 + j] = fmaf(qv[i], kv[j], s[i * 4 + j]);
                    s[i * 4 + j] = fmaf(qv[i], krv[j - i + 3], s[i * 4 + j]);
                }
        }
        #pragma unroll
        for (int i = 0; i < 16; i++) s[i] *= 0.125f;  // 1/sqrt(64)

        if (t0 == u0) {  // diagonal tile: causal mask
            #pragma unroll
            for (int i = 0; i < 4; i++)
                #pragma unroll
                for (int j = 0; j < 4; j++)
                    if (c0 + j > r0 + i) s[i * 4 + j] = -CUDART_INF_F;
        }

        // Online softmax per row (rows replicated across the 16 tx lanes)
        #pragma unroll
        for (int i = 0; i < 4; i++) {
            float rm = fmaxf(fmaxf(s[i * 4 + 0], s[i * 4 + 1]),
                             fmaxf(s[i * 4 + 2], s[i * 4 + 3]));
            #pragma unroll
            for (int off = 1; off < 16; off <<= 1)
                rm = fmaxf(rm, __shfl_xor_sync(0xffffffffu, rm, off));
            float mn    = fmaxf(m_i[i], rm);
            float alpha = __expf(m_i[i] - mn);
            m_i[i] = mn;
            float ps = 0.f;
            #pragma unroll
            for (int j = 0; j < 4; j++) {
                float p = __expf(s[i * 4 + j] - mn);
                s[i * 4 + j] = p;
                ps += p;
            }
            #pragma unroll
            for (int off = 1; off < 16; off <<= 1)
                ps += __shfl_xor_sync(0xffffffffu, ps, off);
            l_i[i] = l_i[i] * alpha + ps;
            #pragma unroll
            for (int j = 0; j < 4; j++) o[i * 4 + j] *= alpha;
            float4 pv = make_float4(s[i * 4 + 0], s[i * 4 + 1], s[i * 4 + 2], s[i * 4 + 3]);
            *(float4*)&as_[(r0 + i) * 64 + c0] = pv;
        }
        __syncthreads();

        // O += A @ V   (4 rows x 4 output cols, 4-wide tt chunks)
        #pragma unroll 4
        for (int tt = 0; tt < 64; tt += 4) {
            float4 a0 = *(const float4*)&as_[(r0 + 0) * 64 + tt];
            float4 a1 = *(const float4*)&as_[(r0 + 1) * 64 + tt];
            float4 a2 = *(const float4*)&as_[(r0 + 2) * 64 + tt];
            float4 a3 = *(const float4*)&as_[(r0 + 3) * 64 + tt];
            float4 v0 = *(const float4*)&vs[(tt + 0) * 64 + c0];
            float4 v1 = *(const float4*)&vs[(tt + 1) * 64 + c0];
            float4 v2 = *(const float4*)&vs[(tt + 2) * 64 + c0];
            float4 v3 = *(const float4*)&vs[(tt + 3) * 64 + c0];
            float av[4][4] = {{a0.x, a0.y, a0.z, a0.w}, {a1.x, a1.y, a1.z, a1.w},
                              {a2.x, a2.y, a2.z, a2.w}, {a3.x, a3.y, a3.z, a3.w}};
            float vv[4][4] = {{v0.x, v0.y, v0.z, v0.w}, {v1.x, v1.y, v1.z, v1.w},
                              {v2.x, v2.y, v2.z, v2.w}, {v3.x, v3.y, v3.z, v3.w}};
            #pragma unroll
            for (int i = 0; i < 4; i++)
                #pragma unroll
                for (int q = 0; q < 4; q++)
                    #pragma unroll
                    for (int j = 0; j < 4; j++)
                        o[i * 4 + j] = fmaf(av[i][q], vv[q][j], o[i * 4 + j]);
        }
    }

    // Epilogue: normalize and store
    float* ob = out + (size_t)b * SEQ * DK;
    #pragma unroll
    for (int i = 0; i < 4; i++) {
        float inv = 1.f / l_i[i];
        float4 r;
        r.x = o[i * 4 + 0] * inv;
        r.y = o[i * 4 + 1] * inv;
        r.z = o[i * 4 + 2] * inv;
        r.w = o[i * 4 + 3] * inv;
        *(float4*)&ob[(size_t)(u0 + r0 + i) * DK + c0] = r;
    }
}

extern "C" void kernel_launch(void* const* d_in, const int* in_sizes, int n_in,
                              void* d_out, int out_size) {
    const float* Q  = (const float*)d_in[0];
    const float* K  = (const float*)d_in[1];
    const float* V  = (const float*)d_in[2];
    const float* Kr = (const float*)d_in[3];
    float* out = (float*)d_out;

    cudaFuncSetAttribute(attn_kernel, cudaFuncAttributeMaxDynamicSharedMemorySize, 98304);

    dim3 tb(32, 8);
    dim3 tg(SEQ / 32, DK / 32, BSZ);
    transpose_kernel<<<tg, tb>>>(Q, 0);
    transpose_kernel<<<tg, tb>>>(K, 1);

    attn_kernel<<<dim3(SEQ / BM, BSZ), 256, 98304>>>(V, Kr, out);
}

// round 5
// speedup vs baseline: 1.8094x; 1.7590x over previous
#include <cuda_runtime.h>
#include <cuda_bf16.h>
#include <cstdint>

#define BSZ 16
#define SEQ 2048
#define DKE 64
#define KR_ROWS 2176

// -------- device-global bf16 split scratch --------
__device__ __align__(16) __nv_bfloat16 g_qhi[BSZ * SEQ * DKE];
__device__ __align__(16) __nv_bfloat16 g_qlo[BSZ * SEQ * DKE];
__device__ __align__(16) __nv_bfloat16 g_khi[BSZ * SEQ * DKE];
__device__ __align__(16) __nv_bfloat16 g_klo[BSZ * SEQ * DKE];
__device__ __align__(16) __nv_bfloat16 g_vthi[BSZ * DKE * SEQ];  // [b][d][t]
__device__ __align__(16) __nv_bfloat16 g_vtlo[BSZ * DKE * SEQ];
__device__ __align__(16) __nv_bfloat16 g_krthi[KR_ROWS * DKE];   // [c][d], c>=SEQ zero

__device__ __forceinline__ uint32_t smem_to_u32(const void* p) {
    uint32_t a;
    asm("{ .reg .u64 t; cvta.to.shared.u64 t, %1; cvt.u32.u64 %0, t; }" : "=r"(a) : "l"(p));
    return a;
}

#define LDSM4(r0, r1, r2, r3, addr) \
    asm volatile("ldmatrix.sync.aligned.m8n8.x4.shared.b16 {%0,%1,%2,%3}, [%4];" \
                 : "=r"(r0), "=r"(r1), "=r"(r2), "=r"(r3) : "r"(addr))

#define MMA16816(d, a, bb0, bb1) \
    asm volatile("mma.sync.aligned.m16n8k16.row.col.f32.bf16.bf16.f32 " \
                 "{%0,%1,%2,%3},{%4,%5,%6,%7},{%8,%9},{%0,%1,%2,%3};" \
                 : "+f"((d)[0]), "+f"((d)[1]), "+f"((d)[2]), "+f"((d)[3]) \
                 : "r"((a)[0]), "r"((a)[1]), "r"((a)[2]), "r"((a)[3]), "r"(bb0), "r"(bb1))

#define C_SCALE 0.1803368801111204f  /* log2(e)/sqrt(64) */

__device__ __forceinline__ float fexp2(float x) {
    x = fmaxf(x, -126.0f);
    float n = rintf(x), f = x - n;
    float r = 0.00133335581464f;
    r = fmaf(r, f, 0.00961812910763f);
    r = fmaf(r, f, 0.0555041086648f);
    r = fmaf(r, f, 0.2402265069591f);
    r = fmaf(r, f, 0.69314718056f);
    r = fmaf(r, f, 1.0f);
    return r * __int_as_float(((int)n + 127) << 23);
}

// -------- prologue --------
__global__ void split_kernel(const float* __restrict__ in,
                             __nv_bfloat16* __restrict__ hi, __nv_bfloat16* __restrict__ lo) {
    int i = blockIdx.x * blockDim.x + threadIdx.x;
    float x = in[i];
    __nv_bfloat16 h = __float2bfloat16(x);
    hi[i] = h;
    lo[i] = __float2bfloat16(x - __bfloat162float(h));
}
__global__ void vsplit_kernel(const float* __restrict__ V) {
    __shared__ float tile[32][33];
    int b = blockIdx.z, s0 = blockIdx.x * 32, d0 = blockIdx.y * 32;
    int tx = threadIdx.x, ty = threadIdx.y;
    const float* ip = V + (size_t)b * SEQ * DKE;
    for (int i = ty; i < 32; i += 8) tile[i][tx] = ip[(size_t)(s0 + i) * DKE + d0 + tx];
    __syncthreads();
    for (int i = ty; i < 32; i += 8) {
        float x = tile[tx][i];
        __nv_bfloat16 h = __float2bfloat16(x);
        size_t oi = ((size_t)b * DKE + d0 + i) * SEQ + s0 + tx;
        g_vthi[oi] = h;
        g_vtlo[oi] = __float2bfloat16(x - __bfloat162float(h));
    }
}
__global__ void krsplit_kernel(const float* __restrict__ Kr) {
    __shared__ float tile[32][33];
    int c0 = blockIdx.x * 32, d0 = blockIdx.y * 32;
    int tx = threadIdx.x, ty = threadIdx.y;
    for (int i = ty; i < 32; i += 8) {
        int c = c0 + tx;
        tile[i][tx] = (c < SEQ) ? Kr[(size_t)(d0 + i) * SEQ + c] : 0.0f;
    }
    __syncthreads();
    for (int i = ty; i < 32; i += 8)
        g_krthi[(size_t)(c0 + i) * DKE + d0 + tx] = __float2bfloat16(tile[tx][i]);
}

// -------- smem layout (bytes) --------
#define KHI_O 0            /* 128 rows x 144B  (64 bf16 + 8 pad) */
#define KLO_O 18432
#define KR_O  36864        /* 256 rows x 144B */
#define VHI_O 73728        /* 64 rows x 272B  (128 bf16 + 8 pad) */
#define VLO_O 91136
#define BS_O  108544       /* f32 128 x 132 */
#define SMEM_TOTAL 176128

__global__ __launch_bounds__(256, 1)
void attn_mma_kernel(float* __restrict__ out) {
    extern __shared__ char smem[];
    const uint32_t sm = smem_to_u32(smem);
    const int tid = threadIdx.x, w = tid >> 5, l = tid & 31;
    const int g = l >> 2, tg = l & 3;
    const int R = w * 16;
    const int ua = R + g, ub = R + g + 8;
    const int b = blockIdx.y;
    const int u0 = (15 - (int)blockIdx.x) * 128;  // big tiles first

    // ---- stage Q into K buffers, build persistent Q fragments ----
    for (int i = tid; i < 1024; i += 256) {
        int r = i >> 3, c = i & 7;
        *(int4*)(smem + KHI_O + r * 144 + c * 16) =
            *(const int4*)(g_qhi + ((size_t)b * SEQ + u0 + r) * DKE + c * 8);
        *(int4*)(smem + KLO_O + r * 144 + c * 16) =
            *(const int4*)(g_qlo + ((size_t)b * SEQ + u0 + r) * DKE + c * 8);
    }
    __syncthreads();

    uint32_t qh[4][4], ql[4][4];
    {
        const int qrow = R + (l & 15);
        const int qko = ((l >> 4) & 1) * 8;
        #pragma unroll
        for (int c = 0; c < 4; c++) {
            uint32_t off = (uint32_t)(qrow * 144 + (c * 16 + qko) * 2);
            LDSM4(qh[c][0], qh[c][1], qh[c][2], qh[c][3], sm + KHI_O + off);
            LDSM4(ql[c][0], ql[c][1], ql[c][2], ql[c][3], sm + KLO_O + off);
        }
    }

    const int brow = l & 7;           // B-fragment address row within 8-tile
    const int bko = (l >> 3) * 8;     // B-fragment k offset (elems)
    float* Bs = (float*)(smem + BS_O);

    float m_a = -1e30f, m_b = -1e30f, l_a = 0.0f, l_b = 0.0f;
    float o[8][4];
    #pragma unroll
    for (int j = 0; j < 8; j++) { o[j][0] = o[j][1] = o[j][2] = o[j][3] = 0.0f; }

    const int nIter = u0 / 128 + 1;
    for (int it = 0; it < nIter; ++it) {
        const int t0 = it * 128;
        const int c_base = 1920 - u0 + t0;
        __syncthreads();  // everyone done with previous tiles before restaging

        for (int i = tid; i < 1024; i += 256) {
            int r = i >> 3, c = i & 7;
            *(int4*)(smem + KHI_O + r * 144 + c * 16) =
                *(const int4*)(g_khi + ((size_t)b * SEQ + t0 + r) * DKE + c * 8);
            *(int4*)(smem + KLO_O + r * 144 + c * 16) =
                *(const int4*)(g_klo + ((size_t)b * SEQ + t0 + r) * DKE + c * 8);
        }
        for (int i = tid; i < 2048; i += 256) {
            int r = i >> 3, c = i & 7;
            *(int4*)(smem + KR_O + r * 144 + c * 16) =
                *(const int4*)(g_krthi + (size_t)(c_base + r) * DKE + c * 8);
        }
        for (int i = tid; i < 1024; i += 256) {
            int d = i >> 4, c = i & 15;
            size_t src = ((size_t)b * DKE + d) * SEQ + t0 + c * 8;
            *(int4*)(smem + VHI_O + d * 272 + c * 16) = *(const int4*)(g_vthi + src);
            *(int4*)(smem + VLO_O + d * 272 + c * 16) = *(const int4*)(g_vtlo + src);
        }
        __syncthreads();

        // ---- S = Q K^T, 3 error-compensated passes ----
        float s[16][4];
        #pragma unroll
        for (int j = 0; j < 16; j++) {
            uint32_t bh[8], bl[8];
            uint32_t ab = (uint32_t)((8 * j + brow) * 144 + bko * 2);
            LDSM4(bh[0], bh[1], bh[2], bh[3], sm + KHI_O + ab);
            LDSM4(bh[4], bh[5], bh[6], bh[7], sm + KHI_O + ab + 64);
            LDSM4(bl[0], bl[1], bl[2], bl[3], sm + KLO_O + ab);
            LDSM4(bl[4], bl[5], bl[6], bl[7], sm + KLO_O + ab + 64);
            float* d = s[j];
            d[0] = d[1] = d[2] = d[3] = 0.0f;
            #pragma unroll
            for (int c = 0; c < 4; c++) {
                MMA16816(d, qh[c], bh[2 * c], bh[2 * c + 1]);
                MMA16816(d, qh[c], bl[2 * c], bl[2 * c + 1]);
                MMA16816(d, ql[c], bh[2 * c], bh[2 * c + 1]);
            }
        }

        // ---- bias GEMM on this warp's 18 window tiles + diagonal-shift scatter ----
        {
            const int j0 = 14 - 2 * w;
            #pragma unroll
            for (int jj = 0; jj < 18; jj++) {
                int j = j0 + jj;  // 0..31
                uint32_t kb[8];
                uint32_t ab = (uint32_t)((8 * j + brow) * 144 + bko * 2);
                LDSM4(kb[0], kb[1], kb[2], kb[3], sm + KR_O + ab);
                LDSM4(kb[4], kb[5], kb[6], kb[7], sm + KR_O + ab + 64);
                float d[4] = {0.0f, 0.0f, 0.0f, 0.0f};
                #pragma unroll
                for (int c = 0; c < 4; c++) {
                    MMA16816(d, qh[c], kb[2 * c], kb[2 * c + 1]);
                    MMA16816(d, ql[c], kb[2 * c], kb[2 * c + 1]);
                }
                int cc = 8 * j + 2 * tg;
                int ta = cc + ua - 127, tb = cc + ub - 127;
                if ((unsigned)ta < 128u)       Bs[ua * 132 + ta] = d[0];
                if ((unsigned)(ta + 1) < 128u) Bs[ua * 132 + ta + 1] = d[1];
                if ((unsigned)tb < 128u)       Bs[ub * 132 + tb] = d[2];
                if ((unsigned)(tb + 1) < 128u) Bs[ub * 132 + tb + 1] = d[3];
            }
            __syncwarp();
        }

        // ---- logits (+ bias, scale, causal mask), online softmax ----
        #pragma unroll
        for (int j = 0; j < 16; j++) {
            int cc = 8 * j + 2 * tg;
            float2 ba = *(float2*)&Bs[ua * 132 + cc];
            float2 bb = *(float2*)&Bs[ub * 132 + cc];
            s[j][0] = (s[j][0] + ba.x) * C_SCALE;
            s[j][1] = (s[j][1] + ba.y) * C_SCALE;
            s[j][2] = (s[j][2] + bb.x) * C_SCALE;
            s[j][3] = (s[j][3] + bb.y) * C_SCALE;
        }
        if (t0 == u0) {
            #pragma unroll
            for (int j = 0; j < 16; j++) {
                int cc = 8 * j + 2 * tg;
                if (cc > ua)     s[j][0] = -1e30f;
                if (cc + 1 > ua) s[j][1] = -1e30f;
                if (cc > ub)     s[j][2] = -1e30f;
                if (cc + 1 > ub) s[j][3] = -1e30f;
            }
        }
        float ma = -1e30f, mb = -1e30f;
        #pragma unroll
        for (int j = 0; j < 16; j++) {
            ma = fmaxf(ma, fmaxf(s[j][0], s[j][1]));
            mb = fmaxf(mb, fmaxf(s[j][2], s[j][3]));
        }
        ma = fmaxf(ma, __shfl_xor_sync(0xffffffffu, ma, 1));
        ma = fmaxf(ma, __shfl_xor_sync(0xffffffffu, ma, 2));
        mb = fmaxf(mb, __shfl_xor_sync(0xffffffffu, mb, 1));
        mb = fmaxf(mb, __shfl_xor_sync(0xffffffffu, mb, 2));
        const float mna = fmaxf(m_a, ma), mnb = fmaxf(m_b, mb);
        const float alfa = fexp2(m_a - mna), alfb = fexp2(m_b - mnb);
        m_a = mna; m_b = mnb;
        float pa = 0.0f, pb = 0.0f;
        #pragma unroll
        for (int j = 0; j < 16; j++) {
            s[j][0] = fexp2(s[j][0] - mna);
            s[j][1] = fexp2(s[j][1] - mna);
            s[j][2] = fexp2(s[j][2] - mnb);
            s[j][3] = fexp2(s[j][3] - mnb);
            pa += s[j][0] + s[j][1];
            pb += s[j][2] + s[j][3];
        }
        pa += __shfl_xor_sync(0xffffffffu, pa, 1);
        pa += __shfl_xor_sync(0xffffffffu, pa, 2);
        pb += __shfl_xor_sync(0xffffffffu, pb, 1);
        pb += __shfl_xor_sync(0xffffffffu, pb, 2);
        l_a = l_a * alfa + pa;
        l_b = l_b * alfb + pb;
        #pragma unroll
        for (int j = 0; j < 8; j++) {
            o[j][0] *= alfa; o[j][1] *= alfa;
            o[j][2] *= alfb; o[j][3] *= alfb;
        }

        // ---- P -> bf16 hi/lo A-fragments (register repack, no smem) ----
        uint32_t ph[16][2], pl[16][2];
        #pragma unroll
        for (int j = 0; j < 16; j++) {
            __nv_bfloat162 h0 = __float22bfloat162_rn(make_float2(s[j][0], s[j][1]));
            __nv_bfloat162 h1 = __float22bfloat162_rn(make_float2(s[j][2], s[j][3]));
            ph[j][0] = *(uint32_t*)&h0;
            ph[j][1] = *(uint32_t*)&h1;
            __nv_bfloat162 l0 = __float22bfloat162_rn(make_float2(
                s[j][0] - __bfloat162float(h0.x), s[j][1] - __bfloat162float(h0.y)));
            __nv_bfloat162 l1 = __float22bfloat162_rn(make_float2(
                s[j][2] - __bfloat162float(h1.x), s[j][3] - __bfloat162float(h1.y)));
            pl[j][0] = *(uint32_t*)&l0;
            pl[j][1] = *(uint32_t*)&l1;
        }

        // ---- O += P V, 3 error-compensated passes ----
        #pragma unroll
        for (int jd = 0; jd < 8; jd++) {
            uint32_t vh[16], vl[16];
            uint32_t vb = (uint32_t)((8 * jd + brow) * 272 + bko * 2);
            LDSM4(vh[0], vh[1], vh[2], vh[3], sm + VHI_O + vb);
            LDSM4(vh[4], vh[5], vh[6], vh[7], sm + VHI_O + vb + 64);
            LDSM4(vh[8], vh[9], vh[10], vh[11], sm + VHI_O + vb + 128);
            LDSM4(vh[12], vh[13], vh[14], vh[15], sm + VHI_O + vb + 192);
            LDSM4(vl[0], vl[1], vl[2], vl[3], sm + VLO_O + vb);
            LDSM4(vl[4], vl[5], vl[6], vl[7], sm + VLO_O + vb + 64);
            LDSM4(vl[8], vl[9], vl[10], vl[11], sm + VLO_O + vb + 128);
            LDSM4(vl[12], vl[13], vl[14], vl[15], sm + VLO_O + vb + 192);
            float* d = o[jd];
            #pragma unroll
            for (int c = 0; c < 8; c++) {
                uint32_t a[4] = {ph[2 * c][0], ph[2 * c][1], ph[2 * c + 1][0], ph[2 * c + 1][1]};
                uint32_t al[4] = {pl[2 * c][0], pl[2 * c][1], pl[2 * c + 1][0], pl[2 * c + 1][1]};
                MMA16816(d, a, vh[2 * c], vh[2 * c + 1]);
                MMA16816(d, a, vl[2 * c], vl[2 * c + 1]);
                MMA16816(d, al, vh[2 * c], vh[2 * c + 1]);
            }
        }
    }

    // ---- epilogue ----
    const float inva = 1.0f / l_a, invb = 1.0f / l_b;
    float* orow_a = out + ((size_t)b * SEQ + u0 + ua) * DKE;
    float* orow_b = out + ((size_t)b * SEQ + u0 + ub) * DKE;
    #pragma unroll
    for (int jd = 0; jd < 8; jd++) {
        int cc = 8 * jd + 2 * tg;
        float2 ra, rb;
        ra.x = o[jd][0] * inva; ra.y = o[jd][1] * inva;
        rb.x = o[jd][2] * invb; rb.y = o[jd][3] * invb;
        *(float2*)(orow_a + cc) = ra;
        *(float2*)(orow_b + cc) = rb;
    }
}

extern "C" void kernel_launch(void* const* d_in, const int* in_sizes, int n_in,
                              void* d_out, int out_size) {
    const float* Q  = (const float*)d_in[0];
    const float* K  = (const float*)d_in[1];
    const float* V  = (const float*)d_in[2];
    const float* Kr = (const float*)d_in[3];
    float* out = (float*)d_out;

    cudaFuncSetAttribute(attn_mma_kernel, cudaFuncAttributeMaxDynamicSharedMemorySize, SMEM_TOTAL);

    __nv_bfloat16 *qhi, *qlo, *khi, *klo;
    cudaGetSymbolAddress((void**)&qhi, g_qhi);
    cudaGetSymbolAddress((void**)&qlo, g_qlo);
    cudaGetSymbolAddress((void**)&khi, g_khi);
    cudaGetSymbolAddress((void**)&klo, g_klo);

    const int n = BSZ * SEQ * DKE;
    split_kernel<<<n / 256, 256>>>(Q, qhi, qlo);
    split_kernel<<<n / 256, 256>>>(K, khi, klo);
    vsplit_kernel<<<dim3(SEQ / 32, DKE / 32, BSZ), dim3(32, 8)>>>(V);
    krsplit_kernel<<<dim3(KR_ROWS / 32, DKE / 32), dim3(32, 8)>>>(Kr);

    attn_mma_kernel<<<dim3(16, BSZ), 256, SMEM_TOTAL>>>(out);
}

// round 6
// speedup vs baseline: 2.4821x; 1.3718x over previous
#include <cuda_runtime.h>
#include <cuda_bf16.h>
#include <cstdint>

#define BSZ 16
#define SEQ 2048
#define DKE 64
#define KR_ROWS 2176

// -------- device-global bf16 split scratch --------
__device__ __align__(16) __nv_bfloat16 g_qhi[BSZ * SEQ * DKE];
__device__ __align__(16) __nv_bfloat16 g_qlo[BSZ * SEQ * DKE];
__device__ __align__(16) __nv_bfloat16 g_khi[BSZ * SEQ * DKE];
__device__ __align__(16) __nv_bfloat16 g_klo[BSZ * SEQ * DKE];
__device__ __align__(16) __nv_bfloat16 g_vthi[BSZ * DKE * SEQ];  // [b][d][t]
__device__ __align__(16) __nv_bfloat16 g_vtlo[BSZ * DKE * SEQ];
__device__ __align__(16) __nv_bfloat16 g_krthi[KR_ROWS * DKE];   // [c][d], c>=SEQ zero

__device__ __forceinline__ uint32_t smem_to_u32(const void* p) {
    uint32_t a;
    asm("{ .reg .u64 t; cvta.to.shared.u64 t, %1; cvt.u32.u64 %0, t; }" : "=r"(a) : "l"(p));
    return a;
}

#define LDSM4(r0, r1, r2, r3, addr) \
    asm volatile("ldmatrix.sync.aligned.m8n8.x4.shared.b16 {%0,%1,%2,%3}, [%4];" \
                 : "=r"(r0), "=r"(r1), "=r"(r2), "=r"(r3) : "r"(addr))

#define MMA16816(d, a, bb0, bb1) \
    asm volatile("mma.sync.aligned.m16n8k16.row.col.f32.bf16.bf16.f32 " \
                 "{%0,%1,%2,%3},{%4,%5,%6,%7},{%8,%9},{%0,%1,%2,%3};" \
                 : "+f"((d)[0]), "+f"((d)[1]), "+f"((d)[2]), "+f"((d)[3]) \
                 : "r"((a)[0]), "r"((a)[1]), "r"((a)[2]), "r"((a)[3]), "r"(bb0), "r"(bb1))

#define CP16(dst, src) \
    asm volatile("cp.async.ca.shared.global [%0], [%1], 16;" :: "r"(dst), "l"(src))
#define CP_COMMIT() asm volatile("cp.async.commit_group;")
#define CP_WAIT0()  asm volatile("cp.async.wait_group 0;")

#define C_SCALE 0.1803368801111204f  /* log2(e)/sqrt(64) */

__device__ __forceinline__ float fexp2(float x) {
    x = fmaxf(x, -126.0f);
    float n = rintf(x), f = x - n;
    float r = 0.00133335581464f;
    r = fmaf(r, f, 0.00961812910763f);
    r = fmaf(r, f, 0.0555041086648f);
    r = fmaf(r, f, 0.2402265069591f);
    r = fmaf(r, f, 0.69314718056f);
    r = fmaf(r, f, 1.0f);
    return r * __int_as_float(((int)n + 127) << 23);
}

// -------- merged prologue: 3208 blocks x 256 threads --------
// blocks [0,512): Q split   [512,1024): K split
// blocks [1024,3072): V transpose+split   [3072,3208): Kr transpose
__global__ void prologue_kernel(const float* __restrict__ Q, const float* __restrict__ K,
                                const float* __restrict__ V, const float* __restrict__ Kr) {
    __shared__ float tile[32][33];
    const int bx = blockIdx.x, tid = threadIdx.x;
    if (bx < 1024) {
        const float* src = (bx < 512) ? Q : K;
        __nv_bfloat16* hi = (bx < 512) ? g_qhi : g_khi;
        __nv_bfloat16* lo = (bx < 512) ? g_qlo : g_klo;
        const int base = (bx & 511) * 4096 + tid * 4;
        #pragma unroll
        for (int k = 0; k < 4; k++) {
            int i = base + k * 1024;
            float4 x = *(const float4*)(src + i);
            __nv_bfloat162 h0 = __float22bfloat162_rn(make_float2(x.x, x.y));
            __nv_bfloat162 h1 = __float22bfloat162_rn(make_float2(x.z, x.w));
            *(__nv_bfloat162*)(hi + i) = h0;
            *(__nv_bfloat162*)(hi + i + 2) = h1;
            __nv_bfloat162 l0 = __float22bfloat162_rn(make_float2(
                x.x - __bfloat162float(h0.x), x.y - __bfloat162float(h0.y)));
            __nv_bfloat162 l1 = __float22bfloat162_rn(make_float2(
                x.z - __bfloat162float(h1.x), x.w - __bfloat162float(h1.y)));
            *(__nv_bfloat162*)(lo + i) = l0;
            *(__nv_bfloat162*)(lo + i + 2) = l1;
        }
    } else if (bx < 3072) {
        const int v = bx - 1024;
        const int b = v >> 7, s0 = (v & 63) * 32, d0 = ((v >> 6) & 1) * 32;
        const int tx = tid & 31, ty = tid >> 5;
        const float* ip = V + (size_t)b * SEQ * DKE;
        for (int i = ty; i < 32; i += 8) tile[i][tx] = ip[(size_t)(s0 + i) * DKE + d0 + tx];
        __syncthreads();
        for (int i = ty; i < 32; i += 8) {
            float x = tile[tx][i];
            __nv_bfloat16 h = __float2bfloat16(x);
            size_t oi = ((size_t)b * DKE + d0 + i) * SEQ + s0 + tx;
            g_vthi[oi] = h;
            g_vtlo[oi] = __float2bfloat16(x - __bfloat162float(h));
        }
    } else {
        const int r = bx - 3072;
        const int c0 = (r % 68) * 32, d0 = (r / 68) * 32;
        const int tx = tid & 31, ty = tid >> 5;
        for (int i = ty; i < 32; i += 8) {
            int c = c0 + tx;
            tile[i][tx] = (c < SEQ) ? Kr[(size_t)(d0 + i) * SEQ + c] : 0.0f;
        }
        __syncthreads();
        for (int i = ty; i < 32; i += 8)
            g_krthi[(size_t)(c0 + i) * DKE + d0 + tx] = __float2bfloat16(tile[tx][i]);
    }
}

// -------- smem layout (bytes) --------
#define KHI_O 0            /* 128 rows x 144B  (64 bf16 + 8 pad) */
#define KLO_O 18432
#define KR_O  36864        /* 256 rows x 144B */
#define VHI_O 73728        /* 64 rows x 272B  (128 bf16 + 8 pad) */
#define VLO_O 91136
#define BS_O  108544       /* f32 128 x 132 */
#define SMEM_TOTAL 176128

__global__ __launch_bounds__(256, 1)
void attn_mma_kernel(float* __restrict__ out) {
    extern __shared__ char smem[];
    const uint32_t sm = smem_to_u32(smem);
    const int tid = threadIdx.x, w = tid >> 5, l = tid & 31;
    const int g = l >> 2, tg = l & 3;
    const int R = w * 16;
    const int ua = R + g, ub = R + g + 8;
    const int b = blockIdx.y;
    const int u0 = (15 - (int)blockIdx.x) * 128;  // big tiles first

    // ---- stage Q into K buffers, build persistent Q fragments ----
    for (int i = tid; i < 1024; i += 256) {
        int r = i >> 3, c = i & 7;
        CP16(sm + KHI_O + r * 144 + c * 16,
             (const char*)(g_qhi + ((size_t)b * SEQ + u0 + r) * DKE + c * 8));
        CP16(sm + KLO_O + r * 144 + c * 16,
             (const char*)(g_qlo + ((size_t)b * SEQ + u0 + r) * DKE + c * 8));
    }
    CP_COMMIT();
    CP_WAIT0();
    __syncthreads();

    uint32_t qh[4][4], ql[4][4];
    {
        const int qrow = R + (l & 15);
        const int qko = ((l >> 4) & 1) * 8;
        #pragma unroll
        for (int c = 0; c < 4; c++) {
            uint32_t off = (uint32_t)(qrow * 144 + (c * 16 + qko) * 2);
            LDSM4(qh[c][0], qh[c][1], qh[c][2], qh[c][3], sm + KHI_O + off);
            LDSM4(ql[c][0], ql[c][1], ql[c][2], ql[c][3], sm + KLO_O + off);
        }
    }

    const int brow = l & 7;
    const int bko = (l >> 3) * 8;
    float* Bs = (float*)(smem + BS_O);

    float m_a = -1e30f, m_b = -1e30f, l_a = 0.0f, l_b = 0.0f;
    float o[8][4];
    #pragma unroll
    for (int j = 0; j < 8; j++) { o[j][0] = o[j][1] = o[j][2] = o[j][3] = 0.0f; }

    const int nIter = u0 / 128 + 1;
    for (int it = 0; it < nIter; ++it) {
        const int t0 = it * 128;
        const int c_base = 1920 - u0 + t0;
        __syncthreads();  // previous tiles fully consumed

        for (int i = tid; i < 1024; i += 256) {
            int r = i >> 3, c = i & 7;
            CP16(sm + KHI_O + r * 144 + c * 16,
                 (const char*)(g_khi + ((size_t)b * SEQ + t0 + r) * DKE + c * 8));
            CP16(sm + KLO_O + r * 144 + c * 16,
                 (const char*)(g_klo + ((size_t)b * SEQ + t0 + r) * DKE + c * 8));
        }
        for (int i = tid; i < 2048; i += 256) {
            int r = i >> 3, c = i & 7;
            CP16(sm + KR_O + r * 144 + c * 16,
                 (const char*)(g_krthi + (size_t)(c_base + r) * DKE + c * 8));
        }
        for (int i = tid; i < 1024; i += 256) {
            int d = i >> 4, c = i & 15;
            size_t src = ((size_t)b * DKE + d) * SEQ + t0 + c * 8;
            CP16(sm + VHI_O + d * 272 + c * 16, (const char*)(g_vthi + src));
            CP16(sm + VLO_O + d * 272 + c * 16, (const char*)(g_vtlo + src));
        }
        CP_COMMIT();
        CP_WAIT0();
        __syncthreads();

        // ---- S = Q K^T, 3 error-compensated passes ----
        float s[16][4];
        #pragma unroll
        for (int j = 0; j < 16; j++) {
            uint32_t bh[8], bl[8];
            uint32_t ab = (uint32_t)((8 * j + brow) * 144 + bko * 2);
            LDSM4(bh[0], bh[1], bh[2], bh[3], sm + KHI_O + ab);
            LDSM4(bh[4], bh[5], bh[6], bh[7], sm + KHI_O + ab + 64);
            LDSM4(bl[0], bl[1], bl[2], bl[3], sm + KLO_O + ab);
            LDSM4(bl[4], bl[5], bl[6], bl[7], sm + KLO_O + ab + 64);
            float* d = s[j];
            d[0] = d[1] = d[2] = d[3] = 0.0f;
            #pragma unroll
            for (int c = 0; c < 4; c++) {
                MMA16816(d, qh[c], bh[2 * c], bh[2 * c + 1]);
                MMA16816(d, qh[c], bl[2 * c], bl[2 * c + 1]);
                MMA16816(d, ql[c], bh[2 * c], bh[2 * c + 1]);
            }
        }

        // ---- bias GEMM (Qhi only) on this warp's 18 window tiles + shift scatter ----
        {
            const int j0 = 14 - 2 * w;
            #pragma unroll
            for (int jj = 0; jj < 18; jj++) {
                int j = j0 + jj;
                uint32_t kb[8];
                uint32_t ab = (uint32_t)((8 * j + brow) * 144 + bko * 2);
                LDSM4(kb[0], kb[1], kb[2], kb[3], sm + KR_O + ab);
                LDSM4(kb[4], kb[5], kb[6], kb[7], sm + KR_O + ab + 64);
                float d[4] = {0.0f, 0.0f, 0.0f, 0.0f};
                #pragma unroll
                for (int c = 0; c < 4; c++)
                    MMA16816(d, qh[c], kb[2 * c], kb[2 * c + 1]);
                int cc = 8 * j + 2 * tg;
                int ta = cc + ua - 127, tb = cc + ub - 127;
                if ((unsigned)ta < 128u)       Bs[ua * 132 + ta] = d[0];
                if ((unsigned)(ta + 1) < 128u) Bs[ua * 132 + ta + 1] = d[1];
                if ((unsigned)tb < 128u)       Bs[ub * 132 + tb] = d[2];
                if ((unsigned)(tb + 1) < 128u) Bs[ub * 132 + tb + 1] = d[3];
            }
            __syncwarp();
        }

        // ---- logits + online softmax ----
        #pragma unroll
        for (int j = 0; j < 16; j++) {
            int cc = 8 * j + 2 * tg;
            float2 ba = *(float2*)&Bs[ua * 132 + cc];
            float2 bb = *(float2*)&Bs[ub * 132 + cc];
            s[j][0] = (s[j][0] + ba.x) * C_SCALE;
            s[j][1] = (s[j][1] + ba.y) * C_SCALE;
            s[j][2] = (s[j][2] + bb.x) * C_SCALE;
            s[j][3] = (s[j][3] + bb.y) * C_SCALE;
        }
        if (t0 == u0) {
            #pragma unroll
            for (int j = 0; j < 16; j++) {
                int cc = 8 * j + 2 * tg;
                if (cc > ua)     s[j][0] = -1e30f;
                if (cc + 1 > ua) s[j][1] = -1e30f;
                if (cc > ub)     s[j][2] = -1e30f;
                if (cc + 1 > ub) s[j][3] = -1e30f;
            }
        }
        float ma = -1e30f, mb = -1e30f;
        #pragma unroll
        for (int j = 0; j < 16; j++) {
            ma = fmaxf(ma, fmaxf(s[j][0], s[j][1]));
            mb = fmaxf(mb, fmaxf(s[j][2], s[j][3]));
        }
        ma = fmaxf(ma, __shfl_xor_sync(0xffffffffu, ma, 1));
        ma = fmaxf(ma, __shfl_xor_sync(0xffffffffu, ma, 2));
        mb = fmaxf(mb, __shfl_xor_sync(0xffffffffu, mb, 1));
        mb = fmaxf(mb, __shfl_xor_sync(0xffffffffu, mb, 2));
        const float mna = fmaxf(m_a, ma), mnb = fmaxf(m_b, mb);
        const float alfa = fexp2(m_a - mna), alfb = fexp2(m_b - mnb);
        m_a = mna; m_b = mnb;
        float pa = 0.0f, pb = 0.0f;
        #pragma unroll
        for (int j = 0; j < 16; j++) {
            s[j][0] = fexp2(s[j][0] - mna);
            s[j][1] = fexp2(s[j][1] - mna);
            s[j][2] = fexp2(s[j][2] - mnb);
            s[j][3] = fexp2(s[j][3] - mnb);
            pa += s[j][0] + s[j][1];
            pb += s[j][2] + s[j][3];
        }
        pa += __shfl_xor_sync(0xffffffffu, pa, 1);
        pa += __shfl_xor_sync(0xffffffffu, pa, 2);
        pb += __shfl_xor_sync(0xffffffffu, pb, 1);
        pb += __shfl_xor_sync(0xffffffffu, pb, 2);
        l_a = l_a * alfa + pa;
        l_b = l_b * alfb + pb;
        #pragma unroll
        for (int j = 0; j < 8; j++) {
            o[j][0] *= alfa; o[j][1] *= alfa;
            o[j][2] *= alfb; o[j][3] *= alfb;
        }

        // ---- P -> bf16 hi/lo A-fragments ----
        uint32_t ph[16][2], pl[16][2];
        #pragma unroll
        for (int j = 0; j < 16; j++) {
            __nv_bfloat162 h0 = __float22bfloat162_rn(make_float2(s[j][0], s[j][1]));
            __nv_bfloat162 h1 = __float22bfloat162_rn(make_float2(s[j][2], s[j][3]));
            ph[j][0] = *(uint32_t*)&h0;
            ph[j][1] = *(uint32_t*)&h1;
            __nv_bfloat162 l0 = __float22bfloat162_rn(make_float2(
                s[j][0] - __bfloat162float(h0.x), s[j][1] - __bfloat162float(h0.y)));
            __nv_bfloat162 l1 = __float22bfloat162_rn(make_float2(
                s[j][2] - __bfloat162float(h1.x), s[j][3] - __bfloat162float(h1.y)));
            pl[j][0] = *(uint32_t*)&l0;
            pl[j][1] = *(uint32_t*)&l1;
        }

        // ---- O += P V, 3 error-compensated passes ----
        #pragma unroll
        for (int jd = 0; jd < 8; jd++) {
            uint32_t vh[16], vl[16];
            uint32_t vb = (uint32_t)((8 * jd + brow) * 272 + bko * 2);
            LDSM4(vh[0], vh[1], vh[2], vh[3], sm + VHI_O + vb);
            LDSM4(vh[4], vh[5], vh[6], vh[7], sm + VHI_O + vb + 64);
            LDSM4(vh[8], vh[9], vh[10], vh[11], sm + VHI_O + vb + 128);
            LDSM4(vh[12], vh[13], vh[14], vh[15], sm + VHI_O + vb + 192);
            LDSM4(vl[0], vl[1], vl[2], vl[3], sm + VLO_O + vb);
            LDSM4(vl[4], vl[5], vl[6], vl[7], sm + VLO_O + vb + 64);
            LDSM4(vl[8], vl[9], vl[10], vl[11], sm + VLO_O + vb + 128);
            LDSM4(vl[12], vl[13], vl[14], vl[15], sm + VLO_O + vb + 192);
            float* d = o[jd];
            #pragma unroll
            for (int c = 0; c < 8; c++) {
                uint32_t a[4] = {ph[2 * c][0], ph[2 * c][1], ph[2 * c + 1][0], ph[2 * c + 1][1]};
                uint32_t al[4] = {pl[2 * c][0], pl[2 * c][1], pl[2 * c + 1][0], pl[2 * c + 1][1]};
                MMA16816(d, a, vh[2 * c], vh[2 * c + 1]);
                MMA16816(d, a, vl[2 * c], vl[2 * c + 1]);
                MMA16816(d, al, vh[2 * c], vh[2 * c + 1]);
            }
        }
    }

    // ---- epilogue ----
    const float inva = 1.0f / l_a, invb = 1.0f / l_b;
    float* orow_a = out + ((size_t)b * SEQ + u0 + ua) * DKE;
    float* orow_b = out + ((size_t)b * SEQ + u0 + ub) * DKE;
    #pragma unroll
    for (int jd = 0; jd < 8; jd++) {
        int cc = 8 * jd + 2 * tg;
        float2 ra, rb;
        ra.x = o[jd][0] * inva; ra.y = o[jd][1] * inva;
        rb.x = o[jd][2] * invb; rb.y = o[jd][3] * invb;
        *(float2*)(orow_a + cc) = ra;
        *(float2*)(orow_b + cc) = rb;
    }
}

extern "C" void kernel_launch(void* const* d_in, const int* in_sizes, int n_in,
                              void* d_out, int out_size) {
    const float* Q  = (const float*)d_in[0];
    const float* K  = (const float*)d_in[1];
    const float* V  = (const float*)d_in[2];
    const float* Kr = (const float*)d_in[3];
    float* out = (float*)d_out;

    cudaFuncSetAttribute(attn_mma_kernel, cudaFuncAttributeMaxDynamicSharedMemorySize, SMEM_TOTAL);

    prologue_kernel<<<3208, 256>>>(Q, K, V, Kr);
    attn_mma_kernel<<<dim3(16, BSZ), 256, SMEM_TOTAL>>>(out);
}